// round 3
// baseline (speedup 1.0000x reference)
#include <cuda_runtime.h>
#include <math.h>

typedef unsigned long long ull;

#define NT    70
#define NSEG  69
#define NS    11
#define OBS   8
#define MAXSLOT 16

__constant__ float c_times[16] = {0.f,2.f,4.f,6.f,8.f,10.f,12.f,14.f,
                                  16.f,18.f,20.f,25.f,30.f,40.f,50.f,60.f};
__constant__ float c_epo[16]   = {0.01713f,0.145f,0.2442f,0.7659f,1.0f,0.8605f,
                                  0.7829f,0.5705f,0.6217f,0.331f,0.3388f,0.3116f,
                                  0.05062f,0.02504f,0.01163f,0.01163f};

// ---- packed f32x2 helpers ----
__device__ __forceinline__ ull pk2(float lo, float hi) {
    ull r; asm("mov.b64 %0, {%1, %2};" : "=l"(r) : "f"(lo), "f"(hi)); return r;
}
__device__ __forceinline__ void upk2(ull v, float& lo, float& hi) {
    asm("mov.b64 {%0, %1}, %2;" : "=f"(lo), "=f"(hi) : "l"(v));
}
__device__ __forceinline__ ull f2fma(ull a, ull b, ull c) {
    ull r; asm("fma.rn.f32x2 %0, %1, %2, %3;" : "=l"(r) : "l"(a), "l"(b), "l"(c)); return r;
}
__device__ __forceinline__ ull f2mul(ull a, ull b) {
    ull r; asm("mul.rn.f32x2 %0, %1, %2;" : "=l"(r) : "l"(a), "l"(b)); return r;
}
__device__ __forceinline__ ull f2add(ull a, ull b) {
    ull r; asm("add.rn.f32x2 %0, %1, %2;" : "=l"(r) : "l"(a), "l"(b)); return r;
}

__device__ __forceinline__ float epo_interp(float t) {
    if (t <= c_times[0]) return c_epo[0];
    #pragma unroll
    for (int k = 1; k < 16; ++k) {
        if (t <= c_times[k]) {
            float w = (t - c_times[k-1]) / (c_times[k] - c_times[k-1]);
            return c_epo[k-1] + w * (c_epo[k] - c_epo[k-1]);
        }
    }
    return c_epo[15];
}

// Packed 11-state derivative. Chain entries (3..10) return RAW diffs x[i-1]-x[i];
// the r factor is folded into the RK4 combine coefficients.
// 3 mul + 11 fma.
__device__ __forceinline__ void deriv2(const ull* __restrict__ x,
                                       ull kE, ull K2P, ull NK2, ull NEG1,
                                       ull* __restrict__ s) {
    ull t1    = f2mul(kE, x[0]);
    ull x2sq  = f2mul(x[1], x[1]);
    ull k2out = f2mul(K2P, x[10]);
    s[0] = f2fma(t1,   NEG1, k2out);   // -k1*E*x1 + k2*out
    s[1] = f2fma(x2sq, NEG1, t1);      //  k1*E*x1 - x2^2
    s[2] = f2fma(NK2,  x[2], x2sq);    //  x2^2 - k2*x3
    #pragma unroll
    for (int i = 3; i <= 10; ++i)
        s[i] = f2fma(x[i], NEG1, x[i-1]);
}

__global__ __launch_bounds__(128, 1) void stats5_kernel(
    const float* __restrict__ params,   // (B,3)
    const float* __restrict__ design,   // (8,)
    const float* __restrict__ noise,    // (B,16)
    float* __restrict__ out,            // true (B,16) then noised (B,16)
    int B)
{
    __shared__ ull   sElo[NSEG], sEmid[NSEG], sEhi[NSEG];
    __shared__ int   sSlot[NT];            // -1 or snapshot slot id
    __shared__ int   sIdxS[OBS];
    __shared__ float sWS[OBS];
    __shared__ ull   sY1[MAXSLOT][128];    // y1 snapshots, per-thread
    __shared__ ull   sY2[MAXSLOT][128];

    const float dt  = 60.0f / 69.0f;
    const int tid = threadIdx.x;

    if (tid < NSEG) {
        float t0 = (float)tid * dt;
        float a = epo_interp(t0);
        float m = epo_interp(t0 + 0.5f * dt);
        float c = epo_interp(t0 + dt);
        sElo[tid]  = pk2(a, a);
        sEmid[tid] = pk2(m, m);
        sEhi[tid]  = pk2(c, c);
    }
    if (tid < OBS) {
        float d = design[tid];
        float u = d * (69.0f / 60.0f);
        int i = (int)floorf(u);
        if (i < 0) i = 0;
        if (i > NSEG - 1) i = NSEG - 1;
        sIdxS[tid] = i;
        sWS[tid]   = u - (float)i;
    }
    __syncthreads();

    if (tid == 0) {
        // mark needed time indices, assign snapshot slots in increasing t
        int needed[NT];
        #pragma unroll 1
        for (int t = 0; t < NT; ++t) needed[t] = 0;
        for (int j = 0; j < OBS; ++j) {
            needed[sIdxS[j]]     = 1;
            needed[sIdxS[j] + 1] = 1;
        }
        int slot = 0;
        #pragma unroll 1
        for (int t = 0; t < NT; ++t)
            sSlot[t] = needed[t] ? slot++ : -1;
    }
    __syncthreads();

    int p = blockIdx.x * blockDim.x + tid;   // pair index
    int nPairs = B >> 1;
    if (p >= nPairs) return;
    int b0 = 2 * p, b1 = 2 * p + 1;

    // Parameters: shift + normcdf(p) * scale
    float k1a  = fmaf(normcdff(params[3*b0+0]), 2.5f,  0.5f);
    float k2a  = fmaf(normcdff(params[3*b0+1]), 0.15f, 0.05f);
    float ra   = 8.0f / fmaf(normcdff(params[3*b0+2]), 6.0f, 4.0f);
    float k1b  = fmaf(normcdff(params[3*b1+0]), 2.5f,  0.5f);
    float k2b  = fmaf(normcdff(params[3*b1+1]), 0.15f, 0.05f);
    float rb   = 8.0f / fmaf(normcdff(params[3*b1+2]), 6.0f, 4.0f);

    const float hdt = 0.5f * dt, dt6 = dt / 6.0f, dt3 = dt / 3.0f;

    const ull NEG1 = pk2(-1.0f, -1.0f);
    const ull K1P  = pk2(k1a, k1b);
    const ull K2P  = pk2(k2a, k2b);
    const ull NK2  = pk2(-k2a, -k2b);
    const ull Hdt  = pk2(hdt, hdt);
    const ull HdtR = pk2(hdt*ra, hdt*rb);
    const ull Dt   = pk2(dt, dt);
    const ull DtR  = pk2(dt*ra, dt*rb);
    const ull G    = pk2(dt6, dt6);
    const ull GR   = pk2(dt6*ra, dt6*rb);
    const ull G2   = pk2(dt3, dt3);
    const ull G2R  = pk2(dt3*ra, dt3*rb);
    const ull C33  = pk2(0.33f, 0.33f);
    const ull C26  = pk2(0.26f, 0.26f);

    ull x[NS], s[NS], xt[NS], xn[NS];
    #pragma unroll
    for (int i = 0; i < NS; ++i) x[i] = 0ULL;
    x[0] = pk2(3.71f, 3.71f);

    // t = 0 snapshot (y1 = 0, y2 = 0.26*3.71)
    {
        int sl = sSlot[0];
        if (sl >= 0) {
            const float y2s = 0.26f * 3.71f;
            sY1[sl][tid] = 0ULL;
            sY2[sl][tid] = pk2(y2s, y2s);
        }
    }

    #pragma unroll 1
    for (int t = 0; t < NSEG; ++t) {
        ull Ea = sElo[t], Em = sEmid[t], Ec = sEhi[t];

        // stage 1
        ull kE = f2mul(K1P, Ea);
        deriv2(x, kE, K2P, NK2, NEG1, s);
        #pragma unroll
        for (int i = 0; i < NS; ++i) {
            ull h = (i < 3) ? Hdt : HdtR;
            ull g = (i < 3) ? G   : GR;
            xt[i] = f2fma(h, s[i], x[i]);
            xn[i] = f2fma(g, s[i], x[i]);
        }

        // stage 2 (E mid)
        kE = f2mul(K1P, Em);
        deriv2(xt, kE, K2P, NK2, NEG1, s);
        #pragma unroll
        for (int i = 0; i < NS; ++i) {
            ull h  = (i < 3) ? Hdt : HdtR;
            ull g2 = (i < 3) ? G2  : G2R;
            xn[i] = f2fma(g2, s[i], xn[i]);
            xt[i] = f2fma(h,  s[i], x[i]);
        }

        // stage 3 (E mid)
        deriv2(xt, kE, K2P, NK2, NEG1, s);
        #pragma unroll
        for (int i = 0; i < NS; ++i) {
            ull d  = (i < 3) ? Dt : DtR;
            ull g2 = (i < 3) ? G2 : G2R;
            xn[i] = f2fma(g2, s[i], xn[i]);
            xt[i] = f2fma(d,  s[i], x[i]);
        }

        // stage 4 (E hi)
        kE = f2mul(K1P, Ec);
        deriv2(xt, kE, K2P, NK2, NEG1, s);
        #pragma unroll
        for (int i = 0; i < NS; ++i) {
            ull g = (i < 3) ? G : GR;
            x[i] = f2fma(g, s[i], xn[i]);
        }

        // Snapshot observables at flagged steps (<=16 of 69), uniform branch
        int sl = sSlot[t + 1];
        if (sl >= 0) {
            ull y1 = f2mul(C33, f2add(x[1], x[2]));
            ull y2 = f2mul(C26, f2add(f2add(x[0], x[1]), x[2]));
            sY1[sl][tid] = y1;
            sY2[sl][tid] = y2;
        }
    }

    // Final design-point interpolation from snapshots
    float*       tr0 = out + (size_t)b0 * 16;
    float*       tr1 = out + (size_t)b1 * 16;
    float*       nz0 = out + (size_t)B * 16 + (size_t)b0 * 16;
    float*       nz1 = out + (size_t)B * 16 + (size_t)b1 * 16;
    const float* ns0 = noise + (size_t)b0 * 16;
    const float* ns1 = noise + (size_t)b1 * 16;

    #pragma unroll 1
    for (int j = 0; j < OBS; ++j) {
        int   i  = sIdxS[j];
        float w  = sWS[j];
        int   sa = sSlot[i];
        int   sb = sSlot[i + 1];
        ull W  = pk2(w, w);
        ull WM = pk2(1.0f - w, 1.0f - w);

        ull o1 = f2fma(WM, sY1[sa][tid], f2mul(W, sY1[sb][tid]));
        ull o2 = f2fma(WM, sY2[sa][tid], f2mul(W, sY2[sb][tid]));

        float a1, b1v, a2, b2v;
        upk2(o1, a1, b1v);
        upk2(o2, a2, b2v);
        tr0[j]     = a1;  tr0[j + 8] = a2;
        tr1[j]     = b1v; tr1[j + 8] = b2v;
        nz0[j]     = fmaf(0.01f, ns0[j],     a1);
        nz0[j + 8] = fmaf(0.01f, ns0[j + 8], a2);
        nz1[j]     = fmaf(0.01f, ns1[j],     b1v);
        nz1[j + 8] = fmaf(0.01f, ns1[j + 8], b2v);
    }
}

extern "C" void kernel_launch(void* const* d_in, const int* in_sizes, int n_in,
                              void* d_out, int out_size) {
    const float* params = (const float*)d_in[0];
    const float* design = (const float*)d_in[1];
    const float* noise  = (const float*)d_in[2];
    float* out = (float*)d_out;
    int B = in_sizes[0] / 3;

    int threads = 128;
    int nPairs = B >> 1;
    int blocks = (nPairs + threads - 1) / threads;
    stats5_kernel<<<blocks, threads>>>(params, design, noise, out, B);
}

// round 4
// speedup vs baseline: 1.2474x; 1.2474x over previous
#include <cuda_runtime.h>
#include <math.h>

typedef unsigned long long ull;

#define NT    70
#define NSEG  69
#define NS    11
#define OBS   8

__constant__ float c_times[16] = {0.f,2.f,4.f,6.f,8.f,10.f,12.f,14.f,
                                  16.f,18.f,20.f,25.f,30.f,40.f,50.f,60.f};
__constant__ float c_epo[16]   = {0.01713f,0.145f,0.2442f,0.7659f,1.0f,0.8605f,
                                  0.7829f,0.5705f,0.6217f,0.331f,0.3388f,0.3116f,
                                  0.05062f,0.02504f,0.01163f,0.01163f};

// ---- packed f32x2 helpers ----
__device__ __forceinline__ ull pk2(float lo, float hi) {
    ull r; asm("mov.b64 %0, {%1, %2};" : "=l"(r) : "f"(lo), "f"(hi)); return r;
}
__device__ __forceinline__ void upk2(ull v, float& lo, float& hi) {
    asm("mov.b64 {%0, %1}, %2;" : "=f"(lo), "=f"(hi) : "l"(v));
}
__device__ __forceinline__ ull f2fma(ull a, ull b, ull c) {
    ull r; asm("fma.rn.f32x2 %0, %1, %2, %3;" : "=l"(r) : "l"(a), "l"(b), "l"(c)); return r;
}
__device__ __forceinline__ ull f2mul(ull a, ull b) {
    ull r; asm("mul.rn.f32x2 %0, %1, %2;" : "=l"(r) : "l"(a), "l"(b)); return r;
}
__device__ __forceinline__ ull f2add(ull a, ull b) {
    ull r; asm("add.rn.f32x2 %0, %1, %2;" : "=l"(r) : "l"(a), "l"(b)); return r;
}

__device__ __forceinline__ float epo_interp(float t) {
    if (t <= c_times[0]) return c_epo[0];
    #pragma unroll
    for (int k = 1; k < 16; ++k) {
        if (t <= c_times[k]) {
            float w = (t - c_times[k-1]) / (c_times[k] - c_times[k-1]);
            return c_epo[k-1] + w * (c_epo[k] - c_epo[k-1]);
        }
    }
    return c_epo[15];
}

__global__ __launch_bounds__(128, 2) void stats5_kernel(
    const float* __restrict__ params,   // (B,3)
    const float* __restrict__ design,   // (8,)
    const float* __restrict__ noise,    // (B,16)
    float* __restrict__ out,            // true (B,16) then noised (B,16)
    int B)
{
    __shared__ ull   sElo[NSEG], sEmid[NSEG], sEhi[NSEG];
    __shared__ float sCoef[NT][OBS];
    __shared__ int   sFlag[NT];

    const float dt  = 60.0f / 69.0f;
    const int tid = threadIdx.x;

    if (tid < NSEG) {
        float t0 = (float)tid * dt;
        float a = epo_interp(t0);
        float m = epo_interp(t0 + 0.5f * dt);
        float c = epo_interp(t0 + dt);
        sElo[tid]  = pk2(a, a);
        sEmid[tid] = pk2(m, m);
        sEhi[tid]  = pk2(c, c);
    }
    if (tid < NT) {
        int flag = 0;
        #pragma unroll
        for (int j = 0; j < OBS; ++j) {
            float d = design[j];
            float u = d * (69.0f / 60.0f);
            int i = (int)floorf(u);
            if (i < 0) i = 0;
            if (i > NSEG - 1) i = NSEG - 1;
            float w = u - (float)i;
            float cf = (tid == i)     ? (1.0f - w) :
                       (tid == i + 1) ? w : 0.0f;
            sCoef[tid][j] = cf;
            if (cf != 0.0f) flag = 1;
        }
        sFlag[tid] = flag;
    }
    __syncthreads();

    int p = blockIdx.x * blockDim.x + tid;
    int nPairs = B >> 1;
    if (p >= nPairs) return;
    int b0 = 2 * p, b1 = 2 * p + 1;

    float k1a  = fmaf(normcdff(params[3*b0+0]), 2.5f,  0.5f);
    float k2a  = fmaf(normcdff(params[3*b0+1]), 0.15f, 0.05f);
    float ra   = 8.0f / fmaf(normcdff(params[3*b0+2]), 6.0f, 4.0f);
    float k1b  = fmaf(normcdff(params[3*b1+0]), 2.5f,  0.5f);
    float k2b  = fmaf(normcdff(params[3*b1+1]), 0.15f, 0.05f);
    float rb   = 8.0f / fmaf(normcdff(params[3*b1+2]), 6.0f, 4.0f);

    const float hdt = 0.5f * dt, dt6 = dt / 6.0f, dt3 = dt / 3.0f;

    const ull NEG1 = pk2(-1.0f, -1.0f);
    const ull K1P  = pk2(k1a, k1b);
    const ull K2P  = pk2(k2a, k2b);
    const ull NK2  = pk2(-k2a, -k2b);
    const ull Hdt  = pk2(hdt, hdt);
    const ull HdtR = pk2(hdt*ra, hdt*rb);
    const ull Dt   = pk2(dt, dt);
    const ull DtR  = pk2(dt*ra, dt*rb);
    const ull G    = pk2(dt6, dt6);
    const ull GR   = pk2(dt6*ra, dt6*rb);
    const ull G2   = pk2(dt3, dt3);
    const ull G2R  = pk2(dt3*ra, dt3*rb);
    const ull C33  = pk2(0.33f, 0.33f);
    const ull C26  = pk2(0.26f, 0.26f);

    ull x[NS], xt[NS], xn[NS];
    #pragma unroll
    for (int i = 0; i < NS; ++i) x[i] = 0ULL;
    x[0] = pk2(3.71f, 3.71f);

    ull o1[OBS], o2[OBS];
    {
        const float y2s = 0.26f * 3.71f;
        #pragma unroll
        for (int j = 0; j < OBS; ++j) {
            float v = sCoef[0][j] * y2s;
            o1[j] = 0ULL;
            o2[j] = pk2(v, v);
        }
    }

    #pragma unroll 1
    for (int t = 0; t < NSEG; ++t) {
        ull Ea = sElo[t], Em = sEmid[t], Ec = sEhi[t];
        ull kE, t1, x2sq, k2out, s;

        // ===== stage 1: read x -> write xt (x + hdt*s), init xn (x + g*s)
        kE    = f2mul(K1P, Ea);
        t1    = f2mul(kE, x[0]);
        x2sq  = f2mul(x[1], x[1]);
        k2out = f2mul(K2P, x[10]);
        #pragma unroll
        for (int i = 10; i >= 3; --i) {
            s = f2fma(x[i], NEG1, x[i-1]);          // raw diff; deriv = r*s
            xn[i] = f2fma(GR,   s, x[i]);
            xt[i] = f2fma(HdtR, s, x[i]);
        }
        s = f2fma(NK2, x[2], x2sq);  xn[2] = f2fma(G, s, x[2]); xt[2] = f2fma(Hdt, s, x[2]);
        s = f2fma(x2sq, NEG1, t1);   xn[1] = f2fma(G, s, x[1]); xt[1] = f2fma(Hdt, s, x[1]);
        s = f2fma(t1, NEG1, k2out);  xn[0] = f2fma(G, s, x[0]); xt[0] = f2fma(Hdt, s, x[0]);

        // ===== stage 2: read xt (old), write xt in place (x + hdt*s), xn += g2*s
        kE    = f2mul(K1P, Em);
        t1    = f2mul(kE, xt[0]);
        x2sq  = f2mul(xt[1], xt[1]);
        k2out = f2mul(K2P, xt[10]);
        #pragma unroll
        for (int i = 10; i >= 3; --i) {             // descending: reads old xt[i-1], xt[i]
            s = f2fma(xt[i], NEG1, xt[i-1]);
            xn[i] = f2fma(G2R,  s, xn[i]);
            xt[i] = f2fma(HdtR, s, x[i]);
        }
        s = f2fma(NK2, xt[2], x2sq); xn[2] = f2fma(G2, s, xn[2]); xt[2] = f2fma(Hdt, s, x[2]);
        s = f2fma(x2sq, NEG1, t1);   xn[1] = f2fma(G2, s, xn[1]); xt[1] = f2fma(Hdt, s, x[1]);
        s = f2fma(t1, NEG1, k2out);  xn[0] = f2fma(G2, s, xn[0]); xt[0] = f2fma(Hdt, s, x[0]);

        // ===== stage 3: read xt (old), write xt in place (x + dt*s), xn += g2*s
        t1    = f2mul(kE, xt[0]);                   // kE (E mid) reused
        x2sq  = f2mul(xt[1], xt[1]);
        k2out = f2mul(K2P, xt[10]);
        #pragma unroll
        for (int i = 10; i >= 3; --i) {
            s = f2fma(xt[i], NEG1, xt[i-1]);
            xn[i] = f2fma(G2R, s, xn[i]);
            xt[i] = f2fma(DtR, s, x[i]);
        }
        s = f2fma(NK2, xt[2], x2sq); xn[2] = f2fma(G2, s, xn[2]); xt[2] = f2fma(Dt, s, x[2]);
        s = f2fma(x2sq, NEG1, t1);   xn[1] = f2fma(G2, s, xn[1]); xt[1] = f2fma(Dt, s, x[1]);
        s = f2fma(t1, NEG1, k2out);  xn[0] = f2fma(G2, s, xn[0]); xt[0] = f2fma(Dt, s, x[0]);

        // ===== stage 4: read xt, x = xn + g*s
        kE    = f2mul(K1P, Ec);
        t1    = f2mul(kE, xt[0]);
        x2sq  = f2mul(xt[1], xt[1]);
        k2out = f2mul(K2P, xt[10]);
        #pragma unroll
        for (int i = 10; i >= 3; --i) {
            s = f2fma(xt[i], NEG1, xt[i-1]);
            x[i] = f2fma(GR, s, xn[i]);
        }
        s = f2fma(NK2, xt[2], x2sq); x[2] = f2fma(G, s, xn[2]);
        s = f2fma(x2sq, NEG1, t1);   x[1] = f2fma(G, s, xn[1]);
        s = f2fma(t1, NEG1, k2out);  x[0] = f2fma(G, s, xn[0]);

        // Observation accumulation — uniform branch, taken on <= 16 of 69 steps
        int tt = t + 1;
        if (sFlag[tt]) {
            ull y1 = f2mul(C33, f2add(x[1], x[2]));
            ull y2 = f2mul(C26, f2add(f2add(x[0], x[1]), x[2]));
            #pragma unroll
            for (int j = 0; j < OBS; ++j) {
                float cf = sCoef[tt][j];
                ull c2 = pk2(cf, cf);
                o1[j] = f2fma(c2, y1, o1[j]);
                o2[j] = f2fma(c2, y2, o2[j]);
            }
        }
    }

    // Write outputs: true_obs rows then noised_obs rows, both packed lanes
    float*       tr0 = out + (size_t)b0 * 16;
    float*       tr1 = out + (size_t)b1 * 16;
    float*       nz0 = out + (size_t)B * 16 + (size_t)b0 * 16;
    float*       nz1 = out + (size_t)B * 16 + (size_t)b1 * 16;
    const float* ns0 = noise + (size_t)b0 * 16;
    const float* ns1 = noise + (size_t)b1 * 16;
    #pragma unroll
    for (int j = 0; j < OBS; ++j) {
        float a1, b1v, a2, b2v;
        upk2(o1[j], a1, b1v);
        upk2(o2[j], a2, b2v);
        tr0[j]     = a1;  tr0[j + 8] = a2;
        tr1[j]     = b1v; tr1[j + 8] = b2v;
        nz0[j]     = fmaf(0.01f, ns0[j],     a1);
        nz0[j + 8] = fmaf(0.01f, ns0[j + 8], a2);
        nz1[j]     = fmaf(0.01f, ns1[j],     b1v);
        nz1[j + 8] = fmaf(0.01f, ns1[j + 8], b2v);
    }
}

extern "C" void kernel_launch(void* const* d_in, const int* in_sizes, int n_in,
                              void* d_out, int out_size) {
    const float* params = (const float*)d_in[0];
    const float* design = (const float*)d_in[1];
    const float* noise  = (const float*)d_in[2];
    float* out = (float*)d_out;
    int B = in_sizes[0] / 3;

    int threads = 128;
    int nPairs = B >> 1;
    int blocks = (nPairs + threads - 1) / threads;
    stats5_kernel<<<blocks, threads>>>(params, design, noise, out, B);
}